// round 4
// baseline (speedup 1.0000x reference)
#include <cuda_runtime.h>
#include <cuda_bf16.h>

// LSTMSimulator: B=8192 independent sequences, T=2048, N_IN=1, N_H=32, N_OUT=1.
// One warp per batch element, persistent over T. Lane l owns gate rows
// {l, l+32, l+64, l+96} of W_hh, stored as PACKED f32x2 K-pairs in registers.
// h is exchanged through shared memory (1 STS + 8 LDS.128 per step) and the
// 128x32 GEMV runs as 64 fma.rn.f32x2 (FFMA2) per step instead of 128 FFMA.
// Output reduce: 5-step shfl.xor butterfly (redux.f32 not available at compute_100).

#define NH 32
#define T_LEN 2048

typedef unsigned long long u64;

__device__ __forceinline__ u64 fma2(u64 a, u64 b, u64 c) {
    u64 d;
    asm("fma.rn.f32x2 %0, %1, %2, %3;" : "=l"(d) : "l"(a), "l"(b), "l"(c));
    return d;
}
__device__ __forceinline__ u64 pack2(float lo, float hi) {
    u64 r;
    asm("mov.b64 %0, {%1, %2};" : "=l"(r) : "f"(lo), "f"(hi));
    return r;
}
__device__ __forceinline__ float sum2(u64 v) {
    float lo, hi;
    asm("mov.b64 {%0, %1}, %2;" : "=f"(lo), "=f"(hi) : "l"(v));
    return lo + hi;
}
__device__ __forceinline__ float frcp(float v) {
    float r;
    asm("rcp.approx.f32 %0, %1;" : "=f"(r) : "f"(v));
    return r;
}
__device__ __forceinline__ float fexp(float v) {       // e^v via ex2.approx
    float r;
    asm("{ .reg .f32 t; mul.f32 t, %1, 0f3FB8AA3B; ex2.approx.f32 %0, t; }"
        : "=f"(r) : "f"(v));
    return r;
}
__device__ __forceinline__ float fsig(float v) {       // 1/(1+e^-v)
    return frcp(1.0f + fexp(-v));
}
__device__ __forceinline__ float ftanhf(float v) {     // sign-safe tanh
    float t = fexp(-2.0f * fabsf(v));
    float r = (1.0f - t) * frcp(1.0f + t);
    return copysignf(r, v);
}

__global__ void __launch_bounds__(128, 2)
lstm_warp_kernel(const float* __restrict__ input,   // [B, T, 1]
                 const float* __restrict__ W_ih,    // [4*NH, 1]
                 const float* __restrict__ W_hh,    // [4*NH, NH]
                 const float* __restrict__ b_ih,    // [4*NH]
                 const float* __restrict__ b_hh,    // [4*NH]
                 const float* __restrict__ W_lin,   // [1, NH]
                 const float* __restrict__ b_lin,   // [1]
                 float* __restrict__ out,           // [B, T, 1]
                 int B, int T)
{
    __shared__ float hbuf[4][NH];   // one h vector per warp in the block

    const int gwarp = (blockIdx.x * blockDim.x + threadIdx.x) >> 5;
    const int w     = threadIdx.x >> 5;
    const int lane  = threadIdx.x & 31;
    if (gwarp >= B) return;

    const float* xin  = input + (size_t)gwarp * T;
    float*       yout = out   + (size_t)gwarp * T;

    // ---- pack per-lane W_hh rows into f32x2 K-pairs (64 x 64-bit regs) ----
    u64 wI2[NH/2], wF2[NH/2], wG2[NH/2], wO2[NH/2];
    {
        const float4* pI = (const float4*)(W_hh + (size_t)(lane      ) * NH);
        const float4* pF = (const float4*)(W_hh + (size_t)(lane + 32 ) * NH);
        const float4* pG = (const float4*)(W_hh + (size_t)(lane + 64 ) * NH);
        const float4* pO = (const float4*)(W_hh + (size_t)(lane + 96 ) * NH);
        #pragma unroll
        for (int q = 0; q < NH / 4; q++) {
            float4 a = pI[q]; wI2[2*q] = pack2(a.x, a.y); wI2[2*q+1] = pack2(a.z, a.w);
            float4 b = pF[q]; wF2[2*q] = pack2(b.x, b.y); wF2[2*q+1] = pack2(b.z, b.w);
            float4 c = pG[q]; wG2[2*q] = pack2(c.x, c.y); wG2[2*q+1] = pack2(c.z, c.w);
            float4 d = pO[q]; wO2[2*q] = pack2(d.x, d.y); wO2[2*q+1] = pack2(d.z, d.w);
        }
    }
    const float uI = W_ih[lane];
    const float uF = W_ih[lane + 32];
    const float uG = W_ih[lane + 64];
    const float uO = W_ih[lane + 96];
    const float bI = b_ih[lane]      + b_hh[lane];
    const float bF = b_ih[lane + 32] + b_hh[lane + 32];
    const float bG = b_ih[lane + 64] + b_hh[lane + 64];
    const float bO = b_ih[lane + 96] + b_hh[lane + 96];
    const float wlin = W_lin[lane];
    const float blin = b_lin[0];

    float h = 0.0f, c = 0.0f;
    hbuf[w][lane] = h;
    __syncwarp();

    #pragma unroll 1
    for (int t = 0; t < T; t++) {
        // fetch all 32 h values as 16 packed pairs (8 x LDS.128)
        u64 hp[NH/2];
        {
            const ulonglong2* hsrc = (const ulonglong2*)hbuf[w];
            #pragma unroll
            for (int q = 0; q < NH / 4; q++) {
                ulonglong2 v = hsrc[q];
                hp[2*q] = v.x; hp[2*q+1] = v.y;
            }
        }
        __syncwarp();   // all lanes have read old h before anyone overwrites

        const float x = __ldg(xin + t);
        u64 aI2 = pack2(fmaf(x, uI, bI), 0.0f);
        u64 aF2 = pack2(fmaf(x, uF, bF), 0.0f);
        u64 aG2 = pack2(fmaf(x, uG, bG), 0.0f);
        u64 aO2 = pack2(fmaf(x, uO, bO), 0.0f);

        #pragma unroll
        for (int j = 0; j < NH / 2; j++) {
            const u64 hj = hp[j];
            aI2 = fma2(hj, wI2[j], aI2);
            aF2 = fma2(hj, wF2[j], aF2);
            aG2 = fma2(hj, wG2[j], aG2);
            aO2 = fma2(hj, wO2[j], aO2);
        }

        const float ig = fsig(sum2(aI2));
        const float fg = fsig(sum2(aF2));
        const float gg = ftanhf(sum2(aG2));
        const float og = fsig(sum2(aO2));

        c = fmaf(fg, c, ig * gg);
        h = og * ftanhf(c);

        hbuf[w][lane] = h;     // publish for next step
        __syncwarp();

        // y_t = sum_l h[l]*W_lin[l] + b_lin  (butterfly; off the critical path)
        float y = h * wlin;
        #pragma unroll
        for (int off = 16; off > 0; off >>= 1)
            y += __shfl_xor_sync(0xffffffffu, y, off);
        if (lane == 0) yout[t] = y + blin;
    }
}

extern "C" void kernel_launch(void* const* d_in, const int* in_sizes, int n_in,
                              void* d_out, int out_size)
{
    const float* input = (const float*)d_in[0];
    const float* W_ih  = (const float*)d_in[1];
    const float* W_hh  = (const float*)d_in[2];
    const float* b_ih  = (const float*)d_in[3];
    const float* b_hh  = (const float*)d_in[4];
    const float* W_lin = (const float*)d_in[5];
    const float* b_lin = (const float*)d_in[6];
    float* out = (float*)d_out;

    const int T = T_LEN;
    const int B = in_sizes[0] / T;           // N_IN == 1

    const int threads = 128;                 // 4 warps -> 4 batch rows per block
    const int blocks  = (B * 32 + threads - 1) / threads;
    lstm_warp_kernel<<<blocks, threads>>>(input, W_ih, W_hh, b_ih, b_hh,
                                          W_lin, b_lin, out, B, T);
}

// round 6
// speedup vs baseline: 1.2740x; 1.2740x over previous
#include <cuda_runtime.h>
#include <cuda_bf16.h>

// LSTMSimulator: B=8192 independent sequences, T=2048, N_IN=1, N_H=32, N_OUT=1.
// One warp per batch element, persistent over T. Lane l owns gate rows
// {l, l+32, l+64, l+96} of W_hh in registers (128 regs); h broadcast via shfl.
// R5 (resubmit after infra failure): deferred y-reduce (butterfly of step t
// hidden under step t+1's GEMV), leaner saturation-safe activations, x prefetch.

#define NH 32
#define T_LEN 2048

__device__ __forceinline__ float fex2n(float v) {      // 2^(-log2e * v) = e^-v
    float r;
    asm("{ .reg .f32 t; mul.f32 t, %1, 0fBFB8AA3B; ex2.approx.f32 %0, t; }"
        : "=f"(r) : "f"(v));
    return r;
}
__device__ __forceinline__ float fex2n2(float v) {     // e^{-2v}
    float r;
    asm("{ .reg .f32 t; mul.f32 t, %1, 0fC038AA3B; ex2.approx.f32 %0, t; }"
        : "=f"(r) : "f"(v));
    return r;
}
__device__ __forceinline__ float frcp(float v) {
    float r;
    asm("rcp.approx.f32 %0, %1;" : "=f"(r) : "f"(v));
    return r;
}
__device__ __forceinline__ float fsig(float v) {       // 1/(1+e^-v): 4 instr
    return frcp(1.0f + fex2n(v));
}
__device__ __forceinline__ float ftanhf(float v) {     // 2/(1+e^-2v) - 1: 5 instr
    // v -> +inf: e^-2v -> 0 -> 2*1-1 = 1;  v -> -inf: e^-2v -> inf -> rcp=0 -> -1
    return fmaf(2.0f, frcp(1.0f + fex2n2(v)), -1.0f);
}

__global__ void __launch_bounds__(128, 3)
lstm_warp_kernel(const float* __restrict__ input,   // [B, T, 1]
                 const float* __restrict__ W_ih,    // [4*NH, 1]
                 const float* __restrict__ W_hh,    // [4*NH, NH]
                 const float* __restrict__ b_ih,    // [4*NH]
                 const float* __restrict__ b_hh,    // [4*NH]
                 const float* __restrict__ W_lin,   // [1, NH]
                 const float* __restrict__ b_lin,   // [1]
                 float* __restrict__ out,           // [B, T, 1]
                 int B, int T)
{
    const int gwarp = (blockIdx.x * blockDim.x + threadIdx.x) >> 5;
    const int lane  = threadIdx.x & 31;
    if (gwarp >= B) return;

    const float* xin  = input + (size_t)gwarp * T;
    float*       yout = out   + (size_t)gwarp * T;

    // ---- load per-lane weights into registers ----
    float wI[NH], wF[NH], wG[NH], wO[NH];
    {
        const float4* pI = (const float4*)(W_hh + (size_t)(lane      ) * NH);
        const float4* pF = (const float4*)(W_hh + (size_t)(lane + 32 ) * NH);
        const float4* pG = (const float4*)(W_hh + (size_t)(lane + 64 ) * NH);
        const float4* pO = (const float4*)(W_hh + (size_t)(lane + 96 ) * NH);
        #pragma unroll
        for (int q = 0; q < NH / 4; q++) {
            float4 a = pI[q]; wI[4*q]=a.x; wI[4*q+1]=a.y; wI[4*q+2]=a.z; wI[4*q+3]=a.w;
            float4 b = pF[q]; wF[4*q]=b.x; wF[4*q+1]=b.y; wF[4*q+2]=b.z; wF[4*q+3]=b.w;
            float4 c = pG[q]; wG[4*q]=c.x; wG[4*q+1]=c.y; wG[4*q+2]=c.z; wG[4*q+3]=c.w;
            float4 d = pO[q]; wO[4*q]=d.x; wO[4*q+1]=d.y; wO[4*q+2]=d.z; wO[4*q+3]=d.w;
        }
    }
    const float uI = W_ih[lane];
    const float uF = W_ih[lane + 32];
    const float uG = W_ih[lane + 64];
    const float uO = W_ih[lane + 96];
    const float bI = b_ih[lane]      + b_hh[lane];
    const float bF = b_ih[lane + 32] + b_hh[lane + 32];
    const float bG = b_ih[lane + 64] + b_hh[lane + 64];
    const float bO = b_ih[lane + 96] + b_hh[lane + 96];
    const float wlin = W_lin[lane];
    const float blin = b_lin[0];

    float h = 0.0f, c = 0.0f;
    float x      = __ldg(xin);            // x_0
    float y_pend = 0.0f;                  // deferred partial h*wlin from step t-1

    #pragma unroll 1
    for (int t = 0; t < T; t++) {
        float aI = fmaf(x, uI, bI);
        float aF = fmaf(x, uF, bF);
        float aG = fmaf(x, uG, bG);
        float aO = fmaf(x, uO, bO);

        // finish previous step's output reduce, hidden under this step's GEMV
        float y = y_pend;
        #pragma unroll
        for (int off = 16; off > 0; off >>= 1)
            y += __shfl_xor_sync(0xffffffffu, y, off);

        #pragma unroll
        for (int k = 0; k < NH; k++) {
            const float hk = __shfl_sync(0xffffffffu, h, k);
            aI = fmaf(hk, wI[k], aI);
            aF = fmaf(hk, wF[k], aF);
            aG = fmaf(hk, wG[k], aG);
            aO = fmaf(hk, wO[k], aO);
        }

        if (t > 0 && lane == 0) yout[t - 1] = y + blin;   // store deferred y_{t-1}
        if (t + 1 < T) x = __ldg(xin + t + 1);            // prefetch x_{t+1}

        const float ig = fsig(aI);
        const float fg = fsig(aF);
        const float gg = ftanhf(aG);
        const float og = fsig(aO);

        c = fmaf(fg, c, ig * gg);
        h = og * ftanhf(c);

        y_pend = h * wlin;      // reduce + store happen next iteration
    }

    // flush final output
    float y = y_pend;
    #pragma unroll
    for (int off = 16; off > 0; off >>= 1)
        y += __shfl_xor_sync(0xffffffffu, y, off);
    if (lane == 0) yout[T - 1] = y + blin;
}

extern "C" void kernel_launch(void* const* d_in, const int* in_sizes, int n_in,
                              void* d_out, int out_size)
{
    const float* input = (const float*)d_in[0];
    const float* W_ih  = (const float*)d_in[1];
    const float* W_hh  = (const float*)d_in[2];
    const float* b_ih  = (const float*)d_in[3];
    const float* b_hh  = (const float*)d_in[4];
    const float* W_lin = (const float*)d_in[5];
    const float* b_lin = (const float*)d_in[6];
    float* out = (float*)d_out;

    const int T = T_LEN;
    const int B = in_sizes[0] / T;           // N_IN == 1

    const int threads = 128;                 // 4 warps -> 4 batch rows per block
    const int blocks  = (B * 32 + threads - 1) / threads;
    lstm_warp_kernel<<<blocks, threads>>>(input, W_ih, W_hh, b_ih, b_hh,
                                          W_lin, b_lin, out, B, T);
}

// round 7
// speedup vs baseline: 1.2934x; 1.0152x over previous
#include <cuda_runtime.h>
#include <cuda_bf16.h>

// LSTMSimulator: B=8192 independent sequences, T=2048, N_IN=1, N_H=32, N_OUT=1.
// One warp per batch element, persistent over T. Lane l owns gate rows
// {l, l+32, l+64, l+96} of W_hh in registers (128 regs); h broadcast via shfl.
// R6: activation scales PRE-FOLDED into weights (i/f/o rows x -log2e, g rows
// x -2log2e) and cell state kept scaled (c_s = -2log2e * c), so every ex2
// consumes a gate value directly. Saves ~9 fma-class ops/step in a kernel
// whose fma pipe is measured ~99% saturated. Deferred y-reduce kept from R5.

#define NH 32
#define T_LEN 2048

__device__ __forceinline__ float fex2(float v) {       // raw 2^v
    float r;
    asm("ex2.approx.f32 %0, %1;" : "=f"(r) : "f"(v));
    return r;
}
__device__ __forceinline__ float frcp(float v) {
    float r;
    asm("rcp.approx.f32 %0, %1;" : "=f"(r) : "f"(v));
    return r;
}
// sigmoid given PRESCALED arg aS = -log2e * a :  1/(1+2^aS)   (FADD + 2 MUFU)
__device__ __forceinline__ float fsig_s(float v) {
    return frcp(1.0f + fex2(v));
}

#define NEG_L    (-1.4426950408889634f)   // -log2(e)
#define NEG_2L   (-2.8853900817779268f)   // -2*log2(e)

__global__ void __launch_bounds__(128, 3)
lstm_warp_kernel(const float* __restrict__ input,   // [B, T, 1]
                 const float* __restrict__ W_ih,    // [4*NH, 1]
                 const float* __restrict__ W_hh,    // [4*NH, NH]
                 const float* __restrict__ b_ih,    // [4*NH]
                 const float* __restrict__ b_hh,    // [4*NH]
                 const float* __restrict__ W_lin,   // [1, NH]
                 const float* __restrict__ b_lin,   // [1]
                 float* __restrict__ out,           // [B, T, 1]
                 int B, int T)
{
    const int gwarp = (blockIdx.x * blockDim.x + threadIdx.x) >> 5;
    const int lane  = threadIdx.x & 31;
    if (gwarp >= B) return;

    const float* xin  = input + (size_t)gwarp * T;
    float*       yout = out   + (size_t)gwarp * T;

    // ---- load per-lane weights into registers, folding activation scales ----
    // i,f,o rows scaled by -log2e  (sigmoid arg), g rows by -2log2e (tanh arg)
    float wI[NH], wF[NH], wG[NH], wO[NH];
    {
        const float4* pI = (const float4*)(W_hh + (size_t)(lane      ) * NH);
        const float4* pF = (const float4*)(W_hh + (size_t)(lane + 32 ) * NH);
        const float4* pG = (const float4*)(W_hh + (size_t)(lane + 64 ) * NH);
        const float4* pO = (const float4*)(W_hh + (size_t)(lane + 96 ) * NH);
        #pragma unroll
        for (int q = 0; q < NH / 4; q++) {
            float4 a = pI[q];
            wI[4*q]=NEG_L*a.x; wI[4*q+1]=NEG_L*a.y; wI[4*q+2]=NEG_L*a.z; wI[4*q+3]=NEG_L*a.w;
            float4 b = pF[q];
            wF[4*q]=NEG_L*b.x; wF[4*q+1]=NEG_L*b.y; wF[4*q+2]=NEG_L*b.z; wF[4*q+3]=NEG_L*b.w;
            float4 c = pG[q];
            wG[4*q]=NEG_2L*c.x; wG[4*q+1]=NEG_2L*c.y; wG[4*q+2]=NEG_2L*c.z; wG[4*q+3]=NEG_2L*c.w;
            float4 d = pO[q];
            wO[4*q]=NEG_L*d.x; wO[4*q+1]=NEG_L*d.y; wO[4*q+2]=NEG_L*d.z; wO[4*q+3]=NEG_L*d.w;
        }
    }
    const float uI = NEG_L  * W_ih[lane];
    const float uF = NEG_L  * W_ih[lane + 32];
    const float uG = NEG_2L * W_ih[lane + 64];
    const float uO = NEG_L  * W_ih[lane + 96];
    const float bI = NEG_L  * (b_ih[lane]      + b_hh[lane]);
    const float bF = NEG_L  * (b_ih[lane + 32] + b_hh[lane + 32]);
    const float bG = NEG_2L * (b_ih[lane + 64] + b_hh[lane + 64]);
    const float bO = NEG_L  * (b_ih[lane + 96] + b_hh[lane + 96]);
    const float wlin = W_lin[lane];
    const float blin = b_lin[0];

    float h = 0.0f;
    float c_s = 0.0f;                     // c_s = -2*log2e * c  (scaled cell)
    float x      = __ldg(xin);            // x_0
    float y_pend = 0.0f;                  // deferred partial h*wlin from t-1

    #pragma unroll 1
    for (int t = 0; t < T; t++) {
        // gate pre-activations arrive already scaled for ex2
        float aI = fmaf(x, uI, bI);
        float aF = fmaf(x, uF, bF);
        float aG = fmaf(x, uG, bG);
        float aO = fmaf(x, uO, bO);

        // finish previous step's output reduce, hidden under this step's GEMV
        float y = y_pend;
        #pragma unroll
        for (int off = 16; off > 0; off >>= 1)
            y += __shfl_xor_sync(0xffffffffu, y, off);

        #pragma unroll
        for (int k = 0; k < NH; k++) {
            const float hk = __shfl_sync(0xffffffffu, h, k);
            aI = fmaf(hk, wI[k], aI);
            aF = fmaf(hk, wF[k], aF);
            aG = fmaf(hk, wG[k], aG);
            aO = fmaf(hk, wO[k], aO);
        }

        if (t > 0 && lane == 0) yout[t - 1] = y + blin;   // store deferred y
        x = __ldg(xin + min(t + 1, T - 1));               // branchless prefetch

        const float ig = fsig_s(aI);                      // sigmoid(i)
        const float fg = fsig_s(aF);                      // sigmoid(f)
        const float og = fsig_s(aO);                      // sigmoid(o)
        // tanh(g) scaled by -2log2e directly: gg_s = -2L*(2r-1) = -4L*r + 2L
        const float rG   = frcp(1.0f + fex2(aG));
        const float gg_s = fmaf(2.0f * NEG_2L, rG, -NEG_2L);

        // c_s = fg * c_s + ig * gg_s      (scaled recurrence, exact in scale)
        c_s = fmaf(fg, c_s, ig * gg_s);

        // tanh(c) = 2*rcp(1 + 2^{c_s}) - 1 ; h = og * tanh(c)
        const float rC = frcp(1.0f + fex2(c_s));
        const float tC = fmaf(2.0f, rC, -1.0f);
        h = og * tC;

        y_pend = h * wlin;      // reduce + store happen next iteration
    }

    // flush final output
    float y = y_pend;
    #pragma unroll
    for (int off = 16; off > 0; off >>= 1)
        y += __shfl_xor_sync(0xffffffffu, y, off);
    if (lane == 0) yout[T - 1] = y + blin;
}

extern "C" void kernel_launch(void* const* d_in, const int* in_sizes, int n_in,
                              void* d_out, int out_size)
{
    const float* input = (const float*)d_in[0];
    const float* W_ih  = (const float*)d_in[1];
    const float* W_hh  = (const float*)d_in[2];
    const float* b_ih  = (const float*)d_in[3];
    const float* b_hh  = (const float*)d_in[4];
    const float* W_lin = (const float*)d_in[5];
    const float* b_lin = (const float*)d_in[6];
    float* out = (float*)d_out;

    const int T = T_LEN;
    const int B = in_sizes[0] / T;           // N_IN == 1

    const int threads = 128;                 // 4 warps -> 4 batch rows per block
    const int blocks  = (B * 32 + threads - 1) / threads;
    lstm_warp_kernel<<<blocks, threads>>>(input, W_ih, W_hh, b_ih, b_hh,
                                          W_lin, b_lin, out, B, T);
}

// round 8
// speedup vs baseline: 1.2934x; 1.0000x over previous
#include <cuda_runtime.h>
#include <cuda_bf16.h>

// LSTMSimulator: B=8192 independent sequences, T=2048, N_IN=1, N_H=32, N_OUT=1.
// One warp per batch element, persistent over T. Lane l owns gate rows
// {l, l+32, l+64, l+96} of W_hh in registers (128 regs); h broadcast via shfl.
// R6: activation scales PRE-FOLDED into weights (i/f/o rows x -log2e, g rows
// x -2log2e) and cell state kept scaled (c_s = -2log2e * c), so every ex2
// consumes a gate value directly. Saves ~9 fma-class ops/step in a kernel
// whose fma pipe is measured ~99% saturated. Deferred y-reduce kept from R5.

#define NH 32
#define T_LEN 2048

__device__ __forceinline__ float fex2(float v) {       // raw 2^v
    float r;
    asm("ex2.approx.f32 %0, %1;" : "=f"(r) : "f"(v));
    return r;
}
__device__ __forceinline__ float frcp(float v) {
    float r;
    asm("rcp.approx.f32 %0, %1;" : "=f"(r) : "f"(v));
    return r;
}
// sigmoid given PRESCALED arg aS = -log2e * a :  1/(1+2^aS)   (FADD + 2 MUFU)
__device__ __forceinline__ float fsig_s(float v) {
    return frcp(1.0f + fex2(v));
}

#define NEG_L    (-1.4426950408889634f)   // -log2(e)
#define NEG_2L   (-2.8853900817779268f)   // -2*log2(e)

__global__ void __launch_bounds__(128, 3)
lstm_warp_kernel(const float* __restrict__ input,   // [B, T, 1]
                 const float* __restrict__ W_ih,    // [4*NH, 1]
                 const float* __restrict__ W_hh,    // [4*NH, NH]
                 const float* __restrict__ b_ih,    // [4*NH]
                 const float* __restrict__ b_hh,    // [4*NH]
                 const float* __restrict__ W_lin,   // [1, NH]
                 const float* __restrict__ b_lin,   // [1]
                 float* __restrict__ out,           // [B, T, 1]
                 int B, int T)
{
    const int gwarp = (blockIdx.x * blockDim.x + threadIdx.x) >> 5;
    const int lane  = threadIdx.x & 31;
    if (gwarp >= B) return;

    const float* xin  = input + (size_t)gwarp * T;
    float*       yout = out   + (size_t)gwarp * T;

    // ---- load per-lane weights into registers, folding activation scales ----
    // i,f,o rows scaled by -log2e  (sigmoid arg), g rows by -2log2e (tanh arg)
    float wI[NH], wF[NH], wG[NH], wO[NH];
    {
        const float4* pI = (const float4*)(W_hh + (size_t)(lane      ) * NH);
        const float4* pF = (const float4*)(W_hh + (size_t)(lane + 32 ) * NH);
        const float4* pG = (const float4*)(W_hh + (size_t)(lane + 64 ) * NH);
        const float4* pO = (const float4*)(W_hh + (size_t)(lane + 96 ) * NH);
        #pragma unroll
        for (int q = 0; q < NH / 4; q++) {
            float4 a = pI[q];
            wI[4*q]=NEG_L*a.x; wI[4*q+1]=NEG_L*a.y; wI[4*q+2]=NEG_L*a.z; wI[4*q+3]=NEG_L*a.w;
            float4 b = pF[q];
            wF[4*q]=NEG_L*b.x; wF[4*q+1]=NEG_L*b.y; wF[4*q+2]=NEG_L*b.z; wF[4*q+3]=NEG_L*b.w;
            float4 c = pG[q];
            wG[4*q]=NEG_2L*c.x; wG[4*q+1]=NEG_2L*c.y; wG[4*q+2]=NEG_2L*c.z; wG[4*q+3]=NEG_2L*c.w;
            float4 d = pO[q];
            wO[4*q]=NEG_L*d.x; wO[4*q+1]=NEG_L*d.y; wO[4*q+2]=NEG_L*d.z; wO[4*q+3]=NEG_L*d.w;
        }
    }
    const float uI = NEG_L  * W_ih[lane];
    const float uF = NEG_L  * W_ih[lane + 32];
    const float uG = NEG_2L * W_ih[lane + 64];
    const float uO = NEG_L  * W_ih[lane + 96];
    const float bI = NEG_L  * (b_ih[lane]      + b_hh[lane]);
    const float bF = NEG_L  * (b_ih[lane + 32] + b_hh[lane + 32]);
    const float bG = NEG_2L * (b_ih[lane + 64] + b_hh[lane + 64]);
    const float bO = NEG_L  * (b_ih[lane + 96] + b_hh[lane + 96]);
    const float wlin = W_lin[lane];
    const float blin = b_lin[0];

    float h = 0.0f;
    float c_s = 0.0f;                     // c_s = -2*log2e * c  (scaled cell)
    float x      = __ldg(xin);            // x_0
    float y_pend = 0.0f;                  // deferred partial h*wlin from t-1

    #pragma unroll 1
    for (int t = 0; t < T; t++) {
        // gate pre-activations arrive already scaled for ex2
        float aI = fmaf(x, uI, bI);
        float aF = fmaf(x, uF, bF);
        float aG = fmaf(x, uG, bG);
        float aO = fmaf(x, uO, bO);

        // finish previous step's output reduce, hidden under this step's GEMV
        float y = y_pend;
        #pragma unroll
        for (int off = 16; off > 0; off >>= 1)
            y += __shfl_xor_sync(0xffffffffu, y, off);

        #pragma unroll
        for (int k = 0; k < NH; k++) {
            const float hk = __shfl_sync(0xffffffffu, h, k);
            aI = fmaf(hk, wI[k], aI);
            aF = fmaf(hk, wF[k], aF);
            aG = fmaf(hk, wG[k], aG);
            aO = fmaf(hk, wO[k], aO);
        }

        if (t > 0 && lane == 0) yout[t - 1] = y + blin;   // store deferred y
        x = __ldg(xin + min(t + 1, T - 1));               // branchless prefetch

        const float ig = fsig_s(aI);                      // sigmoid(i)
        const float fg = fsig_s(aF);                      // sigmoid(f)
        const float og = fsig_s(aO);                      // sigmoid(o)
        // tanh(g) scaled by -2log2e directly: gg_s = -2L*(2r-1) = -4L*r + 2L
        const float rG   = frcp(1.0f + fex2(aG));
        const float gg_s = fmaf(2.0f * NEG_2L, rG, -NEG_2L);

        // c_s = fg * c_s + ig * gg_s      (scaled recurrence, exact in scale)
        c_s = fmaf(fg, c_s, ig * gg_s);

        // tanh(c) = 2*rcp(1 + 2^{c_s}) - 1 ; h = og * tanh(c)
        const float rC = frcp(1.0f + fex2(c_s));
        const float tC = fmaf(2.0f, rC, -1.0f);
        h = og * tC;

        y_pend = h * wlin;      // reduce + store happen next iteration
    }

    // flush final output
    float y = y_pend;
    #pragma unroll
    for (int off = 16; off > 0; off >>= 1)
        y += __shfl_xor_sync(0xffffffffu, y, off);
    if (lane == 0) yout[T - 1] = y + blin;
}

extern "C" void kernel_launch(void* const* d_in, const int* in_sizes, int n_in,
                              void* d_out, int out_size)
{
    const float* input = (const float*)d_in[0];
    const float* W_ih  = (const float*)d_in[1];
    const float* W_hh  = (const float*)d_in[2];
    const float* b_ih  = (const float*)d_in[3];
    const float* b_hh  = (const float*)d_in[4];
    const float* W_lin = (const float*)d_in[5];
    const float* b_lin = (const float*)d_in[6];
    float* out = (float*)d_out;

    const int T = T_LEN;
    const int B = in_sizes[0] / T;           // N_IN == 1

    const int threads = 128;                 // 4 warps -> 4 batch rows per block
    const int blocks  = (B * 32 + threads - 1) / threads;
    lstm_warp_kernel<<<blocks, threads>>>(input, W_ih, W_hh, b_ih, b_hh,
                                          W_lin, b_lin, out, B, T);
}

// round 9
// speedup vs baseline: 1.2943x; 1.0007x over previous
#include <cuda_runtime.h>
#include <cuda_bf16.h>

// LSTMSimulator: B=8192 independent sequences, T=2048, N_IN=1, N_H=32, N_OUT=1.
// One warp per batch element, persistent over T. Lane l owns gate rows
// {l, l+32, l+64, l+96} of W_hh in registers (128 regs); h broadcast via shfl.
// R6: activation scales PRE-FOLDED into weights (i/f/o rows x -log2e, g rows
// x -2log2e) and cell state kept scaled (c_s = -2log2e * c), so every ex2
// consumes a gate value directly. Saves ~9 fma-class ops/step in a kernel
// whose fma pipe is measured ~99% saturated. Deferred y-reduce kept from R5.

#define NH 32
#define T_LEN 2048

__device__ __forceinline__ float fex2(float v) {       // raw 2^v
    float r;
    asm("ex2.approx.f32 %0, %1;" : "=f"(r) : "f"(v));
    return r;
}
__device__ __forceinline__ float frcp(float v) {
    float r;
    asm("rcp.approx.f32 %0, %1;" : "=f"(r) : "f"(v));
    return r;
}
// sigmoid given PRESCALED arg aS = -log2e * a :  1/(1+2^aS)   (FADD + 2 MUFU)
__device__ __forceinline__ float fsig_s(float v) {
    return frcp(1.0f + fex2(v));
}

#define NEG_L    (-1.4426950408889634f)   // -log2(e)
#define NEG_2L   (-2.8853900817779268f)   // -2*log2(e)

__global__ void __launch_bounds__(128, 3)
lstm_warp_kernel(const float* __restrict__ input,   // [B, T, 1]
                 const float* __restrict__ W_ih,    // [4*NH, 1]
                 const float* __restrict__ W_hh,    // [4*NH, NH]
                 const float* __restrict__ b_ih,    // [4*NH]
                 const float* __restrict__ b_hh,    // [4*NH]
                 const float* __restrict__ W_lin,   // [1, NH]
                 const float* __restrict__ b_lin,   // [1]
                 float* __restrict__ out,           // [B, T, 1]
                 int B, int T)
{
    const int gwarp = (blockIdx.x * blockDim.x + threadIdx.x) >> 5;
    const int lane  = threadIdx.x & 31;
    if (gwarp >= B) return;

    const float* xin  = input + (size_t)gwarp * T;
    float*       yout = out   + (size_t)gwarp * T;

    // ---- load per-lane weights into registers, folding activation scales ----
    // i,f,o rows scaled by -log2e  (sigmoid arg), g rows by -2log2e (tanh arg)
    float wI[NH], wF[NH], wG[NH], wO[NH];
    {
        const float4* pI = (const float4*)(W_hh + (size_t)(lane      ) * NH);
        const float4* pF = (const float4*)(W_hh + (size_t)(lane + 32 ) * NH);
        const float4* pG = (const float4*)(W_hh + (size_t)(lane + 64 ) * NH);
        const float4* pO = (const float4*)(W_hh + (size_t)(lane + 96 ) * NH);
        #pragma unroll
        for (int q = 0; q < NH / 4; q++) {
            float4 a = pI[q];
            wI[4*q]=NEG_L*a.x; wI[4*q+1]=NEG_L*a.y; wI[4*q+2]=NEG_L*a.z; wI[4*q+3]=NEG_L*a.w;
            float4 b = pF[q];
            wF[4*q]=NEG_L*b.x; wF[4*q+1]=NEG_L*b.y; wF[4*q+2]=NEG_L*b.z; wF[4*q+3]=NEG_L*b.w;
            float4 c = pG[q];
            wG[4*q]=NEG_2L*c.x; wG[4*q+1]=NEG_2L*c.y; wG[4*q+2]=NEG_2L*c.z; wG[4*q+3]=NEG_2L*c.w;
            float4 d = pO[q];
            wO[4*q]=NEG_L*d.x; wO[4*q+1]=NEG_L*d.y; wO[4*q+2]=NEG_L*d.z; wO[4*q+3]=NEG_L*d.w;
        }
    }
    const float uI = NEG_L  * W_ih[lane];
    const float uF = NEG_L  * W_ih[lane + 32];
    const float uG = NEG_2L * W_ih[lane + 64];
    const float uO = NEG_L  * W_ih[lane + 96];
    const float bI = NEG_L  * (b_ih[lane]      + b_hh[lane]);
    const float bF = NEG_L  * (b_ih[lane + 32] + b_hh[lane + 32]);
    const float bG = NEG_2L * (b_ih[lane + 64] + b_hh[lane + 64]);
    const float bO = NEG_L  * (b_ih[lane + 96] + b_hh[lane + 96]);
    const float wlin = W_lin[lane];
    const float blin = b_lin[0];

    float h = 0.0f;
    float c_s = 0.0f;                     // c_s = -2*log2e * c  (scaled cell)
    float x      = __ldg(xin);            // x_0
    float y_pend = 0.0f;                  // deferred partial h*wlin from t-1

    #pragma unroll 1
    for (int t = 0; t < T; t++) {
        // gate pre-activations arrive already scaled for ex2
        float aI = fmaf(x, uI, bI);
        float aF = fmaf(x, uF, bF);
        float aG = fmaf(x, uG, bG);
        float aO = fmaf(x, uO, bO);

        // finish previous step's output reduce, hidden under this step's GEMV
        float y = y_pend;
        #pragma unroll
        for (int off = 16; off > 0; off >>= 1)
            y += __shfl_xor_sync(0xffffffffu, y, off);

        #pragma unroll
        for (int k = 0; k < NH; k++) {
            const float hk = __shfl_sync(0xffffffffu, h, k);
            aI = fmaf(hk, wI[k], aI);
            aF = fmaf(hk, wF[k], aF);
            aG = fmaf(hk, wG[k], aG);
            aO = fmaf(hk, wO[k], aO);
        }

        if (t > 0 && lane == 0) yout[t - 1] = y + blin;   // store deferred y
        x = __ldg(xin + min(t + 1, T - 1));               // branchless prefetch

        const float ig = fsig_s(aI);                      // sigmoid(i)
        const float fg = fsig_s(aF);                      // sigmoid(f)
        const float og = fsig_s(aO);                      // sigmoid(o)
        // tanh(g) scaled by -2log2e directly: gg_s = -2L*(2r-1) = -4L*r + 2L
        const float rG   = frcp(1.0f + fex2(aG));
        const float gg_s = fmaf(2.0f * NEG_2L, rG, -NEG_2L);

        // c_s = fg * c_s + ig * gg_s      (scaled recurrence, exact in scale)
        c_s = fmaf(fg, c_s, ig * gg_s);

        // tanh(c) = 2*rcp(1 + 2^{c_s}) - 1 ; h = og * tanh(c)
        const float rC = frcp(1.0f + fex2(c_s));
        const float tC = fmaf(2.0f, rC, -1.0f);
        h = og * tC;

        y_pend = h * wlin;      // reduce + store happen next iteration
    }

    // flush final output
    float y = y_pend;
    #pragma unroll
    for (int off = 16; off > 0; off >>= 1)
        y += __shfl_xor_sync(0xffffffffu, y, off);
    if (lane == 0) yout[T - 1] = y + blin;
}

extern "C" void kernel_launch(void* const* d_in, const int* in_sizes, int n_in,
                              void* d_out, int out_size)
{
    const float* input = (const float*)d_in[0];
    const float* W_ih  = (const float*)d_in[1];
    const float* W_hh  = (const float*)d_in[2];
    const float* b_ih  = (const float*)d_in[3];
    const float* b_hh  = (const float*)d_in[4];
    const float* W_lin = (const float*)d_in[5];
    const float* b_lin = (const float*)d_in[6];
    float* out = (float*)d_out;

    const int T = T_LEN;
    const int B = in_sizes[0] / T;           // N_IN == 1

    const int threads = 128;                 // 4 warps -> 4 batch rows per block
    const int blocks  = (B * 32 + threads - 1) / threads;
    lstm_warp_kernel<<<blocks, threads>>>(input, W_ih, W_hh, b_ih, b_hh,
                                          W_lin, b_lin, out, B, T);
}